// round 15
// baseline (speedup 1.0000x reference)
#include <cuda_runtime.h>
#include <math.h>

#define B_SZ 256
#define N_SZ 512
#define D_SZ 256
#define R_SZ 64
#define NT   16         // n-tiles per batch
#define TN   32         // rows per n-tile

// Scratch (allocation-free: __device__ globals)
__device__ float g_WvT[D_SZ * D_SZ];        // WvT[d][e] = Wv[e][d]
__device__ float g_p[B_SZ * D_SZ];          // p = tok @ Wq^T @ Wk
__device__ float g_s[B_SZ * N_SZ];          // masked+scaled scores
__device__ float g_mt[B_SZ * NT];           // tile max
__device__ float g_zt[B_SZ * NT];           // tile sum of exp
__device__ float g_part[B_SZ * NT * D_SZ];  // unnormalized partial g

// ---------------------------------------------------------------------------
// k1_fused: z=0 -> p tile: q = tok@Wq^T (smem-staged), p = q@Wk
//           z=1 -> Wv transpose tile
// grid (8 j/e-tiles, 8 b/d-tiles, 2), 256 thr, ~74 KB dynamic smem (z=0)
// ---------------------------------------------------------------------------
extern __shared__ float k1_dyn[];

__global__ void __launch_bounds__(256) k1_fused(
    const float* __restrict__ tok,   // [256,256]
    const float* __restrict__ Wq,    // [64,256]
    const float* __restrict__ Wk,    // [64,256]
    const float* __restrict__ Wv)    // [256,256]
{
    const int tid = threadIdx.x;

    if (blockIdx.z == 1) {
        // Transpose Wv tile: WvT[d0+i][e0+j] = Wv[e0+j][d0+i]
        __shared__ float T[32][33];
        const int tx = tid & 31, ty = tid >> 5;
        const int e0 = blockIdx.x * 32, d0 = blockIdx.y * 32;
        #pragma unroll
        for (int r = 0; r < 4; r++)
            T[ty + 8 * r][tx] = Wv[(e0 + ty + 8 * r) * D_SZ + d0 + tx];
        __syncthreads();
        #pragma unroll
        for (int r = 0; r < 4; r++)
            g_WvT[(d0 + ty + 8 * r) * D_SZ + e0 + tx] = T[tx][ty + 8 * r];
        return;
    }

    // ---- z == 0: p tile ----
    float* tokS = k1_dyn;                 // [32][260]
    float* WqS  = tokS + 32 * 260;        // [32][260]
    float* qS   = WqS + 32 * 260;         // [32][72]

    const int j0 = blockIdx.x * 32;
    const int b0 = blockIdx.y * 32;

    // stage tok tile [32][256]
    #pragma unroll
    for (int i = 0; i < 32; i++) {
        const int idx = tid + 256 * i;
        const int row = idx >> 8, col = idx & 255;
        tokS[row * 260 + col] = tok[(b0 + row) * D_SZ + col];
    }

    // q accumulation: thread owns (row = tid>>3, r = (tid&7) + 8k, k=0..7)
    const int qrow = tid >> 3, rb = tid & 7;
    float qa[8] = {0.f,0.f,0.f,0.f,0.f,0.f,0.f,0.f};

    for (int c = 0; c < 2; c++) {
        __syncthreads();   // protect WqS reuse / tokS first pass
        #pragma unroll
        for (int i = 0; i < 32; i++) {
            const int idx = tid + 256 * i;
            const int row = idx >> 8, col = idx & 255;
            WqS[row * 260 + col] = Wq[(c * 32 + row) * D_SZ + col];
        }
        __syncthreads();

        for (int d = 0; d < D_SZ; d += 4) {
            const float4 tv = *reinterpret_cast<const float4*>(&tokS[qrow * 260 + d]);
            #pragma unroll
            for (int kk = 0; kk < 4; kk++) {
                const float4 wq = *reinterpret_cast<const float4*>(
                    &WqS[(rb + 8 * kk) * 260 + d]);
                qa[4 * c + kk] += tv.x * wq.x + tv.y * wq.y
                                + tv.z * wq.z + tv.w * wq.w;
            }
        }
    }
    __syncthreads();

    // park q in smem: qS[row][r]
    #pragma unroll
    for (int k = 0; k < 8; k++)
        qS[qrow * 72 + rb + 8 * k] = qa[k];
    __syncthreads();

    // p phase: thread (col = tid&31, rows r0+8k); Wk coalesced from global
    {
        const int col = tid & 31, r0 = tid >> 5;
        float acc[4] = {0.f, 0.f, 0.f, 0.f};
        for (int r = 0; r < R_SZ; r++) {
            const float wkv = Wk[r * D_SZ + j0 + col];
            #pragma unroll
            for (int k = 0; k < 4; k++)
                acc[k] += qS[(r0 + 8 * k) * 72 + r] * wkv;
        }
        #pragma unroll
        for (int k = 0; k < 4; k++)
            g_p[(b0 + r0 + 8 * k) * D_SZ + j0 + col] = acc[k];
    }
}

// ---------------------------------------------------------------------------
// K2a (R13-proven): ONE DRAM read of H, tile in registers.
// ---------------------------------------------------------------------------
__global__ void __launch_bounds__(256) k2a_pass(
    const float* __restrict__ H,
    const int* __restrict__ mask,
    const float* __restrict__ log_scale)
{
    __shared__ __align__(16) float p_s[D_SZ];
    __shared__ float s_s[TN];
    __shared__ __align__(16) float4 part4[8 * 64];   // 8 KB

    const int b = blockIdx.y;
    const int t = blockIdx.x;
    const int n0 = t * TN;
    const int tid = threadIdx.x;
    const int w = tid >> 5, l = tid & 31;

    const float* Hb = H + (size_t)b * N_SZ * D_SZ + (size_t)n0 * D_SZ;

    // 1) Front-batch the 8 H LDG.128 FIRST (no dependence on p)
    float4 f[4][2];
    #pragma unroll
    for (int r = 0; r < 4; r++) {
        const float4* h4 = reinterpret_cast<const float4*>(Hb + (w + 8 * r) * D_SZ);
        f[r][0] = h4[l];
        f[r][1] = h4[l + 32];
    }

    // 2) p load + mask (uniform per warp) + scale, overlapped with H latency
    p_s[tid] = g_p[b * D_SZ + tid];
    int mk[4];
    #pragma unroll
    for (int r = 0; r < 4; r++)
        mk[r] = mask[b * N_SZ + n0 + w + 8 * r];   // uniform addr per warp
    const float inv_scale = 1.f / fmaxf(__expf(log_scale[0]), 0.1f);
    __syncthreads();

    const float4* p4 = reinterpret_cast<const float4*>(p_s);
    const float4 pf0 = p4[l];
    const float4 pf1 = p4[l + 32];

    // 3) Dots + warp reduction; masked scores live in ALL lanes' registers
    float sc[4];
    #pragma unroll
    for (int r = 0; r < 4; r++) {
        sc[r] = f[r][0].x * pf0.x + f[r][0].y * pf0.y
              + f[r][0].z * pf0.z + f[r][0].w * pf0.w
              + f[r][1].x * pf1.x + f[r][1].y * pf1.y
              + f[r][1].z * pf1.z + f[r][1].w * pf1.w;
    }
    #pragma unroll
    for (int off = 16; off > 0; off >>= 1) {
        #pragma unroll
        for (int r = 0; r < 4; r++)
            sc[r] += __shfl_xor_sync(0xffffffffu, sc[r], off);
    }
    float s[4];
    #pragma unroll
    for (int r = 0; r < 4; r++)
        s[r] = mk[r] ? sc[r] * inv_scale : -INFINITY;

    if (l == 0) {
        #pragma unroll
        for (int r = 0; r < 4; r++) {
            s_s[w + 8 * r] = s[r];
            g_s[b * N_SZ + n0 + w + 8 * r] = s[r];
        }
    }
    __syncthreads();

    // 4) Stats: every warp redundantly computes tile max (1 LDS + shfl)
    {
        const float v = s_s[l];
        float vm = v;
        #pragma unroll
        for (int off = 16; off > 0; off >>= 1)
            vm = fmaxf(vm, __shfl_xor_sync(0xffffffffu, vm, off));
        const float mu = (vm == -INFINITY) ? 0.f : vm;     // NaN guard

        if (w == 0) {       // warp 0 also computes Z and stores stats
            float z = __expf(v - mu);                      // exp(-inf)=0
            #pragma unroll
            for (int off = 16; off > 0; off >>= 1)
                z += __shfl_xor_sync(0xffffffffu, z, off);
            if (l == 0) {
                g_mt[b * NT + t] = vm;
                g_zt[b * NT + t] = z;
            }
        }

        #pragma unroll
        for (int r = 0; r < 4; r++)
            s[r] = __expf(s[r] - mu);
    }

    // 5) Phase 2: pure register accumulation (no barrier needed)
    float4 acc0 = make_float4(0.f, 0.f, 0.f, 0.f);
    float4 acc1 = make_float4(0.f, 0.f, 0.f, 0.f);
    #pragma unroll
    for (int r = 0; r < 4; r++) {
        const float wn = s[r];
        acc0.x += wn * f[r][0].x;  acc0.y += wn * f[r][0].y;
        acc0.z += wn * f[r][0].z;  acc0.w += wn * f[r][0].w;
        acc1.x += wn * f[r][1].x;  acc1.y += wn * f[r][1].y;
        acc1.z += wn * f[r][1].z;  acc1.w += wn * f[r][1].w;
    }
    part4[w * 64 + l]      = acc0;    // cols [4l, 4l+4)
    part4[w * 64 + 32 + l] = acc1;    // cols [128+4l, ...)
    __syncthreads();

    // 6) Cross-warp sum, thread tid owns column tid
    const float* partf = reinterpret_cast<const float*>(part4);
    float acc = 0.f;
    #pragma unroll
    for (int ww = 0; ww < 8; ww++)
        acc += partf[ww * D_SZ + tid];
    g_part[(b * NT + t) * D_SZ + tid] = acc;
}

// ---------------------------------------------------------------------------
// K2b fused v3 (R12-proven): grid (4 e-quarters, 256 b).
// ---------------------------------------------------------------------------
__global__ void __launch_bounds__(256) k2b_fused(
    float* __restrict__ alpha_out,
    float* __restrict__ ctx)
{
    __shared__ float f_s[NT];
    __shared__ float sm_M, sm_invZ;
    __shared__ float gr[D_SZ];
    __shared__ __align__(16) float red[16][68];   // [d-group][64 e + pad]
    const int b = blockIdx.y;
    const int q = blockIdx.x;          // e-quarter
    const int e0 = q * 64;
    const int tid = threadIdx.x;

    if (tid < 32) {
        const float m_t = (tid < NT) ? g_mt[b * NT + tid] : -INFINITY;
        const float z_t = (tid < NT) ? g_zt[b * NT + tid] : 0.f;
        float M = m_t;
        #pragma unroll
        for (int off = 16; off > 0; off >>= 1)
            M = fmaxf(M, __shfl_xor_sync(0xffffffffu, M, off));
        const float e = (m_t == -INFINITY) ? 0.f : __expf(m_t - M);
        float Z = z_t * e;
        #pragma unroll
        for (int off = 16; off > 0; off >>= 1)
            Z += __shfl_xor_sync(0xffffffffu, Z, off);
        const float invZ = 1.f / Z;
        if (tid < NT) f_s[tid] = e * invZ;
        if (tid == 0) { sm_M = M; sm_invZ = invZ; }
    }
    __syncthreads();

    const float M = sm_M, invZ = sm_invZ;

    // exact alpha (only the q==0 CTA column writes it)
    if (q == 0) {
        alpha_out[b * N_SZ + tid] = __expf(g_s[b * N_SZ + tid] - M) * invZ;
        alpha_out[b * N_SZ + tid + 256] =
            __expf(g_s[b * N_SZ + tid + 256] - M) * invZ;
    }

    // g[b,d] = sum_t f_t * g_part[b,t,d]  -> smem (redundant per quarter)
    float acc = 0.f;
    #pragma unroll
    for (int t = 0; t < NT; t++)
        acc += f_s[t] * g_part[(b * NT + t) * D_SZ + tid];
    gr[tid] = acc;
    __syncthreads();

    // ctx partials: thread (c4 = tid&15 -> 4 e-cols, dg = tid>>4 -> 16 d's)
    {
        const int c4 = tid & 15;            // e-quad index
        const int dg = tid >> 4;            // d-group (16 d's)
        const int d0 = dg * 16;
        const float4* wv4 = reinterpret_cast<const float4*>(
            g_WvT + (size_t)d0 * D_SZ + e0 + 4 * c4);
        float4 a = make_float4(0.f, 0.f, 0.f, 0.f);
        #pragma unroll
        for (int dd = 0; dd < 16; dd++) {
            const float4 wv = wv4[dd * (D_SZ / 4)];
            const float sv = gr[d0 + dd];
            a.x += sv * wv.x;  a.y += sv * wv.y;
            a.z += sv * wv.z;  a.w += sv * wv.w;
        }
        *reinterpret_cast<float4*>(&red[dg][4 * c4]) = a;   // STS.128
    }
    __syncthreads();

    if (tid < 64) {
        float c = 0.f;
        #pragma unroll
        for (int dg = 0; dg < 16; dg++)
            c += red[dg][tid];
        ctx[b * D_SZ + e0 + tid] = c;
    }
}

// ---------------------------------------------------------------------------
extern "C" void kernel_launch(void* const* d_in, const int* in_sizes, int n_in,
                              void* d_out, int out_size) {
    const float* tok  = (const float*)d_in[0];
    const float* H    = (const float*)d_in[1];
    const int* mask   = (const int*)d_in[2];
    const float* Wq   = (const float*)d_in[3];
    const float* Wk   = (const float*)d_in[4];
    const float* Wv   = (const float*)d_in[5];
    const float* ls   = (const float*)d_in[6];

    float* out_alpha = (float*)d_out;                 // [256,512]
    float* out_ctx   = out_alpha + B_SZ * N_SZ;       // [256,256]

    const int dyn = (32 * 260 + 32 * 260 + 32 * 72) * sizeof(float); // ~74 KB
    cudaFuncSetAttribute(k1_fused,
                         cudaFuncAttributeMaxDynamicSharedMemorySize, dyn);

    k1_fused<<<dim3(8, 8, 2), 256, dyn>>>(tok, Wq, Wk, Wv);
    k2a_pass<<<dim3(NT, B_SZ), 256>>>(H, mask, ls);
    k2b_fused<<<dim3(4, B_SZ), 256>>>(out_alpha, out_ctx);
}

// round 17
// speedup vs baseline: 1.0011x; 1.0011x over previous
#include <cuda_runtime.h>
#include <math.h>

#define B_SZ 256
#define N_SZ 512
#define D_SZ 256
#define R_SZ 64
#define NT   16         // n-tiles per batch
#define TN   32         // rows per n-tile

// Scratch (allocation-free: __device__ globals)
__device__ float g_WvT[D_SZ * D_SZ];        // WvT[d][e] = Wv[e][d]
__device__ float g_q[B_SZ * R_SZ];          // q = tok @ Wq^T
__device__ float g_s[B_SZ * N_SZ];          // masked+scaled scores
__device__ float g_mt[B_SZ * NT];           // tile max
__device__ float g_zt[B_SZ * NT];           // tile sum of exp
__device__ float g_part[B_SZ * NT * D_SZ];  // unnormalized partial g

// ---------------------------------------------------------------------------
// kq: z=0 (x<2): q[b,r] = sum_d tok[b,d]*Wq[r,d]  (32x32 NT tiles, K=256)
//     z=1:       WvT transpose tile
// grid (8, 8, 2), 256 thr
// ---------------------------------------------------------------------------
__global__ void __launch_bounds__(256) kq_prep(
    const float* __restrict__ tok,   // [256,256]
    const float* __restrict__ Wq,    // [64,256]
    const float* __restrict__ Wv)    // [256,256]
{
    const int tid = threadIdx.x, tx = tid & 31, ty = tid >> 5;

    if (blockIdx.z == 1) {
        __shared__ float T[32][33];
        const int e0 = blockIdx.x * 32, d0 = blockIdx.y * 32;
        #pragma unroll
        for (int r = 0; r < 4; r++)
            T[ty + 8 * r][tx] = Wv[(e0 + ty + 8 * r) * D_SZ + d0 + tx];
        __syncthreads();
        #pragma unroll
        for (int r = 0; r < 4; r++)
            g_WvT[(d0 + ty + 8 * r) * D_SZ + e0 + tx] = T[tx][ty + 8 * r];
        return;
    }

    if (blockIdx.x >= 2) return;     // q is only 64 wide -> 2 x-tiles

    __shared__ float As[32][33];     // tok rows
    __shared__ float Bs[32][33];     // Wq rows
    const int r0 = blockIdx.x * 32;  // r-tile
    const int b0 = blockIdx.y * 32;  // b-tile
    float acc[4] = {0.f, 0.f, 0.f, 0.f};

    for (int d0 = 0; d0 < D_SZ; d0 += 32) {
        #pragma unroll
        for (int r = 0; r < 4; r++) {
            const int row = ty + 8 * r;
            As[row][tx] = tok[(b0 + row) * D_SZ + d0 + tx];
            Bs[row][tx] = Wq[(r0 + row) * D_SZ + d0 + tx];
        }
        __syncthreads();
        #pragma unroll
        for (int kk = 0; kk < 32; kk++) {
            const float bv = Bs[tx][kk];
            #pragma unroll
            for (int r = 0; r < 4; r++)
                acc[r] += As[ty + 8 * r][kk] * bv;
        }
        __syncthreads();
    }
    #pragma unroll
    for (int r = 0; r < 4; r++)
        g_q[(b0 + ty + 8 * r) * R_SZ + r0 + tx] = acc[r];
}

// ---------------------------------------------------------------------------
// K2a v3: ONE DRAM read of H, tile in registers.  p computed in-CTA from
// q[b]·Wk inside the H DRAM-latency shadow (replaces the k1 launch).
// ---------------------------------------------------------------------------
__global__ void __launch_bounds__(256) k2a_pass(
    const float* __restrict__ H,
    const int* __restrict__ mask,
    const float* __restrict__ log_scale,
    const float* __restrict__ Wk)    // [64,256]
{
    __shared__ __align__(16) float p_s[D_SZ];
    __shared__ float q_s[R_SZ];
    __shared__ float s_s[TN];
    __shared__ __align__(16) float4 part4[8 * 64];   // 8 KB

    const int b = blockIdx.y;
    const int t = blockIdx.x;
    const int n0 = t * TN;
    const int tid = threadIdx.x;
    const int w = tid >> 5, l = tid & 31;

    const float* Hb = H + (size_t)b * N_SZ * D_SZ + (size_t)n0 * D_SZ;

    // 1) Front-batch the 8 H LDG.128 FIRST (they cover everything below)
    float4 f[4][2];
    #pragma unroll
    for (int r = 0; r < 4; r++) {
        const float4* h4 = reinterpret_cast<const float4*>(Hb + (w + 8 * r) * D_SZ);
        f[r][0] = h4[l];
        f[r][1] = h4[l + 32];
    }

    // 2) q load + mask (uniform per warp) + scale, in the H shadow
    if (tid < R_SZ) q_s[tid] = g_q[b * R_SZ + tid];
    int mk[4];
    #pragma unroll
    for (int r = 0; r < 4; r++)
        mk[r] = mask[b * N_SZ + n0 + w + 8 * r];   // uniform addr per warp
    const float inv_scale = 1.f / fmaxf(__expf(log_scale[0]), 0.1f);
    __syncthreads();

    // 3) p[b,tid] = sum_r q[r] * Wk[r,tid]  (coalesced, L1/L2-resident Wk)
    {
        float c0 = 0.f, c1 = 0.f, c2 = 0.f, c3 = 0.f;
        #pragma unroll 4
        for (int r = 0; r < R_SZ; r += 4) {
            c0 += q_s[r]     * Wk[(r)     * D_SZ + tid];
            c1 += q_s[r + 1] * Wk[(r + 1) * D_SZ + tid];
            c2 += q_s[r + 2] * Wk[(r + 2) * D_SZ + tid];
            c3 += q_s[r + 3] * Wk[(r + 3) * D_SZ + tid];
        }
        p_s[tid] = (c0 + c1) + (c2 + c3);
    }
    __syncthreads();

    const float4* p4 = reinterpret_cast<const float4*>(p_s);
    const float4 pf0 = p4[l];
    const float4 pf1 = p4[l + 32];

    // 4) Dots + warp reduction; masked scores in ALL lanes' registers
    float sc[4];
    #pragma unroll
    for (int r = 0; r < 4; r++) {
        sc[r] = f[r][0].x * pf0.x + f[r][0].y * pf0.y
              + f[r][0].z * pf0.z + f[r][0].w * pf0.w
              + f[r][1].x * pf1.x + f[r][1].y * pf1.y
              + f[r][1].z * pf1.z + f[r][1].w * pf1.w;
    }
    #pragma unroll
    for (int off = 16; off > 0; off >>= 1) {
        #pragma unroll
        for (int r = 0; r < 4; r++)
            sc[r] += __shfl_xor_sync(0xffffffffu, sc[r], off);
    }
    float s[4];
    #pragma unroll
    for (int r = 0; r < 4; r++)
        s[r] = mk[r] ? sc[r] * inv_scale : -INFINITY;

    if (l == 0) {
        #pragma unroll
        for (int r = 0; r < 4; r++) {
            s_s[w + 8 * r] = s[r];
            g_s[b * N_SZ + n0 + w + 8 * r] = s[r];
        }
    }
    __syncthreads();

    // 5) Stats: every warp redundantly computes tile max (1 LDS + shfl)
    {
        const float v = s_s[l];
        float vm = v;
        #pragma unroll
        for (int off = 16; off > 0; off >>= 1)
            vm = fmaxf(vm, __shfl_xor_sync(0xffffffffu, vm, off));
        const float mu = (vm == -INFINITY) ? 0.f : vm;     // NaN guard

        if (w == 0) {       // warp 0 also computes Z and stores stats
            float z = __expf(v - mu);                      // exp(-inf)=0
            #pragma unroll
            for (int off = 16; off > 0; off >>= 1)
                z += __shfl_xor_sync(0xffffffffu, z, off);
            if (l == 0) {
                g_mt[b * NT + t] = vm;
                g_zt[b * NT + t] = z;
            }
        }

        #pragma unroll
        for (int r = 0; r < 4; r++)
            s[r] = __expf(s[r] - mu);
    }

    // 6) Phase 2: pure register accumulation (no barrier needed)
    float4 acc0 = make_float4(0.f, 0.f, 0.f, 0.f);
    float4 acc1 = make_float4(0.f, 0.f, 0.f, 0.f);
    #pragma unroll
    for (int r = 0; r < 4; r++) {
        const float wn = s[r];
        acc0.x += wn * f[r][0].x;  acc0.y += wn * f[r][0].y;
        acc0.z += wn * f[r][0].z;  acc0.w += wn * f[r][0].w;
        acc1.x += wn * f[r][1].x;  acc1.y += wn * f[r][1].y;
        acc1.z += wn * f[r][1].z;  acc1.w += wn * f[r][1].w;
    }
    part4[w * 64 + l]      = acc0;    // cols [4l, 4l+4)
    part4[w * 64 + 32 + l] = acc1;    // cols [128+4l, ...)
    __syncthreads();

    // 7) Cross-warp sum, thread tid owns column tid
    const float* partf = reinterpret_cast<const float*>(part4);
    float acc = 0.f;
    #pragma unroll
    for (int ww = 0; ww < 8; ww++)
        acc += partf[ww * D_SZ + tid];
    g_part[(b * NT + t) * D_SZ + tid] = acc;
}

// ---------------------------------------------------------------------------
// K2b fused v3 (proven): grid (4 e-quarters, 256 b).
// ---------------------------------------------------------------------------
__global__ void __launch_bounds__(256) k2b_fused(
    float* __restrict__ alpha_out,
    float* __restrict__ ctx)
{
    __shared__ float f_s[NT];
    __shared__ float sm_M, sm_invZ;
    __shared__ float gr[D_SZ];
    __shared__ __align__(16) float red[16][68];   // [d-group][64 e + pad]
    const int b = blockIdx.y;
    const int q = blockIdx.x;          // e-quarter
    const int e0 = q * 64;
    const int tid = threadIdx.x;

    if (tid < 32) {
        const float m_t = (tid < NT) ? g_mt[b * NT + tid] : -INFINITY;
        const float z_t = (tid < NT) ? g_zt[b * NT + tid] : 0.f;
        float M = m_t;
        #pragma unroll
        for (int off = 16; off > 0; off >>= 1)
            M = fmaxf(M, __shfl_xor_sync(0xffffffffu, M, off));
        const float e = (m_t == -INFINITY) ? 0.f : __expf(m_t - M);
        float Z = z_t * e;
        #pragma unroll
        for (int off = 16; off > 0; off >>= 1)
            Z += __shfl_xor_sync(0xffffffffu, Z, off);
        const float invZ = 1.f / Z;
        if (tid < NT) f_s[tid] = e * invZ;
        if (tid == 0) { sm_M = M; sm_invZ = invZ; }
    }
    __syncthreads();

    const float M = sm_M, invZ = sm_invZ;

    // exact alpha (only the q==0 CTA column writes it)
    if (q == 0) {
        alpha_out[b * N_SZ + tid] = __expf(g_s[b * N_SZ + tid] - M) * invZ;
        alpha_out[b * N_SZ + tid + 256] =
            __expf(g_s[b * N_SZ + tid + 256] - M) * invZ;
    }

    // g[b,d] = sum_t f_t * g_part[b,t,d]  -> smem (redundant per quarter)
    float acc = 0.f;
    #pragma unroll
    for (int t = 0; t < NT; t++)
        acc += f_s[t] * g_part[(b * NT + t) * D_SZ + tid];
    gr[tid] = acc;
    __syncthreads();

    // ctx partials: thread (c4 = tid&15 -> 4 e-cols, dg = tid>>4 -> 16 d's)
    {
        const int c4 = tid & 15;            // e-quad index
        const int dg = tid >> 4;            // d-group (16 d's)
        const int d0 = dg * 16;
        const float4* wv4 = reinterpret_cast<const float4*>(
            g_WvT + (size_t)d0 * D_SZ + e0 + 4 * c4);
        float4 a = make_float4(0.f, 0.f, 0.f, 0.f);
        #pragma unroll
        for (int dd = 0; dd < 16; dd++) {
            const float4 wv = wv4[dd * (D_SZ / 4)];
            const float sv = gr[d0 + dd];
            a.x += sv * wv.x;  a.y += sv * wv.y;
            a.z += sv * wv.z;  a.w += sv * wv.w;
        }
        *reinterpret_cast<float4*>(&red[dg][4 * c4]) = a;   // STS.128
    }
    __syncthreads();

    if (tid < 64) {
        float c = 0.f;
        #pragma unroll
        for (int dg = 0; dg < 16; dg++)
            c += red[dg][tid];
        ctx[b * D_SZ + e0 + tid] = c;
    }
}

// ---------------------------------------------------------------------------
extern "C" void kernel_launch(void* const* d_in, const int* in_sizes, int n_in,
                              void* d_out, int out_size) {
    const float* tok  = (const float*)d_in[0];
    const float* H    = (const float*)d_in[1];
    const int* mask   = (const int*)d_in[2];
    const float* Wq   = (const float*)d_in[3];
    const float* Wk   = (const float*)d_in[4];
    const float* Wv   = (const float*)d_in[5];
    const float* ls   = (const float*)d_in[6];

    float* out_alpha = (float*)d_out;                 // [256,512]
    float* out_ctx   = out_alpha + B_SZ * N_SZ;       // [256,256]

    kq_prep<<<dim3(8, 8, 2), 256>>>(tok, Wq, Wv);
    k2a_pass<<<dim3(NT, B_SZ), 256>>>(H, mask, ls, Wk);
    k2b_fused<<<dim3(4, B_SZ), 256>>>(out_alpha, out_ctx);
}